// round 10
// baseline (speedup 1.0000x reference)
#include <cuda_runtime.h>
#include <math.h>

#define NMAX  12288
#define QB    128             // threads per block
#define NB    768             // persistent blocks: 6/SM x 148 = 888 >= 768, co-resident
#define NCHK  (NMAX / QB)     // 96 compaction chunks (one block each, 1 pt/thread)
#define SBLK  (NMAX / QB)     // 96 strain blocks
#define QW    256             // queries per window (2 per thread)
#define TCAP  ((NMAX / 16) + 12)  // worst-case slice (12288/16=768 at S=16) + pad

struct CMat { float m[9]; float s; };

// ---- persistent scratch (zero-init at load; monotone counters, no resets) ----
__device__ float4 g_cand[NMAX];                 // globally-ordered compacted {x,y,z,|w|^2}
__device__ int    g_cidx[NMAX];                 // compact slot -> original index
__device__ int    g_ccnt[NCHK];                 // per-chunk inside counts
__device__ int    g_ncomp;                      // total inside count
__device__ unsigned long long g_best[NMAX];     // ~((ord(d)<<32)|slot); 0 = armed
__device__ double g_bsum[SBLK];
__device__ int    g_bcnt[SBLK];
__device__ unsigned int g_c0, g_c1, g_c2, g_c3; // monotone barrier/ticket counters

__device__ __forceinline__ unsigned int ford(float f) {
    unsigned int u = __float_as_uint(f);
    return (u & 0x80000000u) ? ~u : (u | 0x80000000u);
}
__device__ __forceinline__ float finv(unsigned int o) {
    unsigned int u = (o & 0x80000000u) ? (o ^ 0x80000000u) : ~o;
    return __uint_as_float(u);
}

// monotone grid barrier (no reset -> no stale-spinner hazard across replays)
__device__ __forceinline__ void gbar(unsigned int* ctr) {
    __syncthreads();
    if (threadIdx.x == 0) {
        __threadfence();
        unsigned int v = atomicAdd(ctr, 1u);
        unsigned int target = (v / NB + 1u) * NB;
        while (*(volatile unsigned int*)ctr < target) __nanosleep(32);
        __threadfence();
    }
    __syncthreads();
}

// ============================================================
// One persistent kernel:
// count -> gbar -> compact(global order) -> gbar -> NN -> gbar -> strain
// ============================================================
__global__ void __launch_bounds__(QB, 6) k_all(const float* __restrict__ new_xyz,
                                               const float* __restrict__ xyz,
                                               const float* __restrict__ gt_sdf,
                                               CMat C, float* __restrict__ out) {
    __shared__ float4 tile[TCAP];         // ~12.5 KB
    __shared__ int    s_w[4];
    __shared__ int    s_c[NCHK];
    __shared__ double s_rd[QB];
    __shared__ int    s_ri[QB];
    __shared__ int    s_last;

    int tid = threadIdx.x, lane = tid & 31, wid = tid >> 5;
    int b   = blockIdx.x;

    // ---------------- Phase 0a: per-chunk counts (blocks 0..95) -------------
    if (b < NCHK) {
        int i = b * QB + tid;
        bool f = gt_sdf[i] < 1e-8f;
        unsigned bal = __ballot_sync(0xffffffffu, f);
        if (lane == 0) s_w[wid] = __popc(bal);
        __syncthreads();
        if (tid == 0) g_ccnt[b] = s_w[0] + s_w[1] + s_w[2] + s_w[3];
    }

    gbar(&g_c0);

    // ---------------- Phase 0b: globally-ordered compaction (blocks 0..95) --
    if (b < NCHK) {
        if (tid < NCHK) s_c[tid] = g_ccnt[tid];
        __syncthreads();
        int base = 0, tot = 0;
        #pragma unroll 8
        for (int j = 0; j < NCHK; ++j) { int v = s_c[j]; if (j < b) base += v; tot += v; }

        int i = b * QB + tid;
        bool f = gt_sdf[i] < 1e-8f;
        unsigned bal = __ballot_sync(0xffffffffu, f);
        int pre = __popc(bal & ((1u << lane) - 1u));
        if (lane == 0) s_w[wid] = __popc(bal);
        __syncthreads();
        int woff = 0;
        #pragma unroll
        for (int w = 0; w < 4; ++w) if (w < wid) woff += s_w[w];
        if (f) {
            int pos = base + woff + pre;               // global index-ordered slot
            float x = new_xyz[3 * i + 0];
            float y = new_xyz[3 * i + 1];
            float z = new_xyz[3 * i + 2];
            g_cand[pos] = make_float4(x, y, z, x * x + y * y + z * z);
            g_cidx[pos] = i;
        }
        if (b == 0 && tid == 0) g_ncomp = tot;
    }

    gbar(&g_c1);

    // ---------------- Phase 1: NN, one uniform item per block ----------------
    {
        int ncomp   = g_ncomp;
        int windows = (ncomp + QW - 1) / QW;           // ~24
        int S       = NB / windows;                    // slices per window (~32)
        int used    = windows * S;

        if (b < used && ncomp > 0) {
            int widx  = b % windows;
            int slice = b / windows;
            int qw0   = widx * QW;
            int lo    = (int)((long long)slice * ncomp / S);
            int hi    = (int)((long long)(slice + 1) * ncomp / S);
            int cntc  = hi - lo;

            for (int k = tid; k < cntc; k += QB)
                tile[k] = g_cand[lo + k];
            if (tid < 12)                              // pad for batch-4 + prefetch
                tile[cntc + tid] = make_float4(0.f, 0.f, 0.f, 1e30f);
            __syncthreads();

            if (cntc > 0) {                            // block-uniform
                int ql0 = qw0 + tid, ql1 = qw0 + QB + tid;
                bool qa0 = (ql0 < ncomp), qa1 = (ql1 < ncomp);
                float4 w0 = g_cand[min(ql0, ncomp - 1)];
                float4 w1 = g_cand[min(ql1, ncomp - 1)];
                float ax0 = -2.f * w0.x, ay0 = -2.f * w0.y, az0 = -2.f * w0.z;
                float ax1 = -2.f * w1.x, ay1 = -2.f * w1.y, az1 = -2.f * w1.z;
                int sk0 = ql0 - lo, sk1 = ql1 - lo;    // self slots within slice

                // block-uniform: does this slice overlap this query window?
                bool overlap = (lo < qw0 + QW) && (hi > qw0);

                int cntc4 = (cntc + 3) & ~3;
                float best0 = 3.0e38f, best1 = 3.0e38f;
                int   kb0 = 0, kb1 = 0;

                float4 c0 = tile[0], c1 = tile[1], c2 = tile[2], c3 = tile[3];
                if (!overlap) {
                    for (int k = 0; k < cntc4; k += 4) {
                        float4 n0 = tile[k+4], n1 = tile[k+5], n2 = tile[k+6], n3 = tile[k+7];
                        float dA0 = fmaf(c0.x, ax0, fmaf(c0.y, ay0, fmaf(c0.z, az0, c0.w)));
                        float dA1 = fmaf(c1.x, ax0, fmaf(c1.y, ay0, fmaf(c1.z, az0, c1.w)));
                        float dA2 = fmaf(c2.x, ax0, fmaf(c2.y, ay0, fmaf(c2.z, az0, c2.w)));
                        float dA3 = fmaf(c3.x, ax0, fmaf(c3.y, ay0, fmaf(c3.z, az0, c3.w)));
                        float dB0 = fmaf(c0.x, ax1, fmaf(c0.y, ay1, fmaf(c0.z, az1, c0.w)));
                        float dB1 = fmaf(c1.x, ax1, fmaf(c1.y, ay1, fmaf(c1.z, az1, c1.w)));
                        float dB2 = fmaf(c2.x, ax1, fmaf(c2.y, ay1, fmaf(c2.z, az1, c2.w)));
                        float dB3 = fmaf(c3.x, ax1, fmaf(c3.y, ay1, fmaf(c3.z, az1, c3.w)));
                        float mA = fminf(fminf(dA0, dA1), fminf(dA2, dA3));
                        float mB = fminf(fminf(dB0, dB1), fminf(dB2, dB3));
                        if (mA < best0) { best0 = mA; kb0 = k; }
                        if (mB < best1) { best1 = mB; kb1 = k; }
                        c0 = n0; c1 = n1; c2 = n2; c3 = n3;
                    }
                } else {
                    for (int k = 0; k < cntc4; k += 4) {
                        float4 n0 = tile[k+4], n1 = tile[k+5], n2 = tile[k+6], n3 = tile[k+7];
                        float dA0 = fmaf(c0.x, ax0, fmaf(c0.y, ay0, fmaf(c0.z, az0, c0.w)));
                        float dA1 = fmaf(c1.x, ax0, fmaf(c1.y, ay0, fmaf(c1.z, az0, c1.w)));
                        float dA2 = fmaf(c2.x, ax0, fmaf(c2.y, ay0, fmaf(c2.z, az0, c2.w)));
                        float dA3 = fmaf(c3.x, ax0, fmaf(c3.y, ay0, fmaf(c3.z, az0, c3.w)));
                        float dB0 = fmaf(c0.x, ax1, fmaf(c0.y, ay1, fmaf(c0.z, az1, c0.w)));
                        float dB1 = fmaf(c1.x, ax1, fmaf(c1.y, ay1, fmaf(c1.z, az1, c1.w)));
                        float dB2 = fmaf(c2.x, ax1, fmaf(c2.y, ay1, fmaf(c2.z, az1, c2.w)));
                        float dB3 = fmaf(c3.x, ax1, fmaf(c3.y, ay1, fmaf(c3.z, az1, c3.w)));
                        if (__any_sync(0xffffffffu, ((unsigned)(sk0 - k) < 4u) |
                                                    ((unsigned)(sk1 - k) < 4u))) {
                            dA0 = (k + 0 == sk0) ? 3e38f : dA0;
                            dA1 = (k + 1 == sk0) ? 3e38f : dA1;
                            dA2 = (k + 2 == sk0) ? 3e38f : dA2;
                            dA3 = (k + 3 == sk0) ? 3e38f : dA3;
                            dB0 = (k + 0 == sk1) ? 3e38f : dB0;
                            dB1 = (k + 1 == sk1) ? 3e38f : dB1;
                            dB2 = (k + 2 == sk1) ? 3e38f : dB2;
                            dB3 = (k + 3 == sk1) ? 3e38f : dB3;
                        }
                        float mA = fminf(fminf(dA0, dA1), fminf(dA2, dA3));
                        float mB = fminf(fminf(dB0, dB1), fminf(dB2, dB3));
                        if (mA < best0) { best0 = mA; kb0 = k; }
                        if (mB < best1) { best1 = mB; kb1 = k; }
                        c0 = n0; c1 = n1; c2 = n2; c3 = n3;
                    }
                }

                // recovery: first element of winning batch with d == best
                if (qa0) {
                    int bi = kb0; bool found = false;
                    #pragma unroll
                    for (int i2 = 0; i2 < 4; ++i2) {
                        float4 c = tile[kb0 + i2];
                        float d = fmaf(c.x, ax0, fmaf(c.y, ay0, fmaf(c.z, az0, c.w)));
                        bool self = overlap && (kb0 + i2 == sk0);
                        if (!found && !self && d == best0) { bi = kb0 + i2; found = true; }
                    }
                    unsigned long long key =
                        ((unsigned long long)ford(best0) << 32) | (unsigned int)(lo + bi);
                    atomicMax(&g_best[ql0], ~key);     // max(~key) == min(key)
                }
                if (qa1) {
                    int bi = kb1; bool found = false;
                    #pragma unroll
                    for (int i2 = 0; i2 < 4; ++i2) {
                        float4 c = tile[kb1 + i2];
                        float d = fmaf(c.x, ax1, fmaf(c.y, ay1, fmaf(c.z, az1, c.w)));
                        bool self = overlap && (kb1 + i2 == sk1);
                        if (!found && !self && d == best1) { bi = kb1 + i2; found = true; }
                    }
                    unsigned long long key =
                        ((unsigned long long)ford(best1) << 32) | (unsigned int)(lo + bi);
                    atomicMax(&g_best[ql1], ~key);
                }
            }
        }
    }

    gbar(&g_c2);

    // ---------------- Phase 2: strain + reduction (blocks 0..95) ----------
    if (b >= SBLK) return;

    int ncomp = g_ncomp;
    int slot = b * QB + tid;                          // compact query slot
    double qsq = 0.0;
    int cnt = 0;
    unsigned long long kp = g_best[slot];
    g_best[slot] = 0ULL;                              // re-arm for next replay
    if (kp != 0ULL && slot < ncomp) {
        unsigned long long key = ~kp;
        float deff = finv((unsigned int)(key >> 32));
        int   nslot = (int)(unsigned int)(key & 0xffffffffu);
        int   i  = g_cidx[slot];
        int   nn = g_cidx[nslot];
        float wqx = new_xyz[3 * i + 0], wqy = new_xyz[3 * i + 1], wqz = new_xyz[3 * i + 2];
        float sqi = wqx * wqx + wqy * wqy + wqz * wqz;
        float mind2 = deff + sqi;                     // add back sq_i
        if (mind2 > 1e-16f) {                         // inside & (nn_d > 1e-8)
            cnt = 1;
            float wnx = new_xyz[3 * nn + 0], wny = new_xyz[3 * nn + 1], wnz = new_xyz[3 * nn + 2];
            float xi0 = xyz[3 * i + 0],  xi1 = xyz[3 * i + 1],  xi2 = xyz[3 * i + 2];
            float xn0 = xyz[3 * nn + 0], xn1 = xyz[3 * nn + 1], xn2 = xyz[3 * nn + 2];
            float du = (wnx - xn0) - (wqx - xi0);     // dm = motion[nn] - motion[i]
            float dv = (wny - xn1) - (wqy - xi1);
            float dw = (wnz - xn2) - (wqz - xi2);
            float dx = wnx - wqx + 1e-8f;
            float dy = wny - wqy + 1e-8f;
            float dz = wnz - wqz + 1e-8f;
            float e0 = du / dx, e1 = dv / dy, e2 = dw / dz;
            float e3 = (du / dy + dv / dx) * 0.5f;
            float e4 = (du / dz + dw / dx) * 0.5f;
            float e5 = (dw / dy + dv / dz) * 0.5f;
            float r0 = C.m[0] * e0 + C.m[1] * e1 + C.m[2] * e2;
            float r1 = C.m[3] * e0 + C.m[4] * e1 + C.m[5] * e2;
            float r2 = C.m[6] * e0 + C.m[7] * e1 + C.m[8] * e2;
            float q  = e0 * r0 + e1 * r1 + e2 * r2
                     + C.s * (e3 * e3 + e4 * e4 + e5 * e5);
            qsq = (double)q * (double)q;
        }
    }
    s_rd[tid] = qsq;
    s_ri[tid] = cnt;
    __syncthreads();
    #pragma unroll
    for (int o = QB / 2; o > 0; o >>= 1) {            // deterministic tree
        if (tid < o) { s_rd[tid] += s_rd[tid + o]; s_ri[tid] += s_ri[tid + o]; }
        __syncthreads();
    }
    if (tid == 0) {
        g_bsum[b] = s_rd[0];
        g_bcnt[b] = s_ri[0];
        __threadfence();
        unsigned int v = atomicAdd(&g_c3, 1u);
        s_last = ((v % SBLK) == SBLK - 1);            // monotone ticket
    }
    __syncthreads();

    if (s_last) {
        __threadfence();
        double s = 0.0; int c = 0;
        if (tid < SBLK) { s = g_bsum[tid]; c = g_bcnt[tid]; }
        s_rd[tid] = s; s_ri[tid] = c;
        __syncthreads();
        #pragma unroll
        for (int o = QB / 2; o > 0; o >>= 1) {
            if (tid < o) { s_rd[tid] += s_rd[tid + o]; s_ri[tid] += s_ri[tid + o]; }
            __syncthreads();
        }
        if (tid == 0)
            out[0] = (float)(sqrt(s_rd[0]) / (double)s_ri[0]);
    }
}

// ============================================================
extern "C" void kernel_launch(void* const* d_in, const int* in_sizes, int n_in,
                              void* d_out, int out_size) {
    const float* new_xyz = (const float*)d_in[0];
    const float* xyz     = (const float*)d_in[1];
    const float* gt_sdf  = (const float*)d_in[2];

    CMat C;
    {
        const double EP = 0.21, VP = 0.4;
        double A[3][3] = {{1.0/EP, -VP/EP, -VP/EP},
                          {-VP/EP, 1.0/EP, -VP/EP},
                          {-VP,    -VP,    1.0/EP}};
        double det = A[0][0]*(A[1][1]*A[2][2]-A[1][2]*A[2][1])
                   - A[0][1]*(A[1][0]*A[2][2]-A[1][2]*A[2][0])
                   + A[0][2]*(A[1][0]*A[2][1]-A[1][1]*A[2][0]);
        double inv[3][3];
        inv[0][0] = (A[1][1]*A[2][2]-A[1][2]*A[2][1])/det;
        inv[0][1] = (A[0][2]*A[2][1]-A[0][1]*A[2][2])/det;
        inv[0][2] = (A[0][1]*A[1][2]-A[0][2]*A[1][1])/det;
        inv[1][0] = (A[1][2]*A[2][0]-A[1][0]*A[2][2])/det;
        inv[1][1] = (A[0][0]*A[2][2]-A[0][2]*A[2][0])/det;
        inv[1][2] = (A[0][2]*A[1][0]-A[0][0]*A[1][2])/det;
        inv[2][0] = (A[1][0]*A[2][1]-A[1][1]*A[2][0])/det;
        inv[2][1] = (A[0][1]*A[2][0]-A[0][0]*A[2][1])/det;
        inv[2][2] = (A[0][0]*A[1][1]-A[0][1]*A[1][0])/det;
        for (int i = 0; i < 3; i++)
            for (int j = 0; j < 3; j++)
                C.m[i * 3 + j] = (float)inv[i][j];
        C.s = (float)(EP / (2.0 * (1.0 + VP)));
    }

    k_all<<<NB, QB>>>(new_xyz, xyz, gt_sdf, C, (float*)d_out);
}